// round 7
// baseline (speedup 1.0000x reference)
#include <cuda_runtime.h>
#include <math.h>

#define N2 512
#define DM 256
#define NSPLIT 16
#define KS 16            // k-width per split block
#define TILE 128         // 4 tiles per dim; symmetric pairs = 10

__device__ float g_gram[NSPLIT][N2 * N2];   // partial Gram sums
__device__ float g_norm[N2];
__device__ float g_ts[N2];
__device__ int   g_perm[N2];
__device__ float g_part[N2];

// ---------------------------------------------------------------------------
// K1: symmetric split-k Gram GEMM. 10 tile-pairs (128x128) x 16 k-splits =
// 160 blocks x 256 threads, 8x8 microtile, single k-chunk (one barrier).
// Blocks 0..63 additionally compute target ranks + row norms.
// ---------------------------------------------------------------------------
__global__ void __launch_bounds__(256) dist_kernel(
    const float* __restrict__ E, const float* __restrict__ T)
{
    __shared__ float At[KS][132];   // [k][row], pad 132
    __shared__ float Bt[KS][132];

    const int tid  = threadIdx.x;
    const int lane = tid & 31;
    const int w    = tid >> 5;

    // ---- fused rank-by-count + row norm on blocks 0..63 ----
    if (blockIdx.x < 64) {
        const int e = blockIdx.x * 8 + w;
        const float tv = __ldg(&T[e]);
        int cnt = 0;
        #pragma unroll
        for (int c = 0; c < 16; c++) {
            int jj = lane + c * 32;
            float o = __ldg(&T[jj]);
            cnt += (o < tv || (o == tv && jj < e)) ? 1 : 0;
        }
        float nrm = 0.0f;
        #pragma unroll
        for (int c = 0; c < 8; c++) {
            float v = __ldg(&E[e * DM + lane + c * 32]);
            nrm = fmaf(v, v, nrm);
        }
        #pragma unroll
        for (int o = 16; o > 0; o >>= 1) {
            cnt += __shfl_xor_sync(0xffffffffu, cnt, o);
            nrm += __shfl_xor_sync(0xffffffffu, nrm, o);
        }
        if (lane == 0) { g_ts[cnt] = tv; g_perm[cnt] = e; g_norm[e] = nrm; }
    }

    // ---- decode block -> (tile pair a<=b over 4; k split) ----
    const int pr    = blockIdx.x >> 4;
    const int split = blockIdx.x & 15;
    int a = 0, rem = pr, len = 4;
    while (rem >= len) { rem -= len; a++; len--; }
    const int b = a + rem;
    const int kbase = split * KS;

    // ---- loaders: r = row in 128-tile, cq = k half ----
    const int r  = tid >> 1;     // 0..127
    const int cq = tid & 1;      // 0..1
    const float* Ea = E + (a * TILE + r) * DM + kbase + cq * 8;
    const float* Eb = E + (b * TILE + r) * DM + kbase + cq * 8;

    float4 a1 = *reinterpret_cast<const float4*>(Ea);
    float4 a2 = *reinterpret_cast<const float4*>(Ea + 4);
    float4 b1 = *reinterpret_cast<const float4*>(Eb);
    float4 b2 = *reinterpret_cast<const float4*>(Eb + 4);

    const int kb = cq * 8;
    At[kb + 0][r] = a1.x; At[kb + 1][r] = a1.y;
    At[kb + 2][r] = a1.z; At[kb + 3][r] = a1.w;
    At[kb + 4][r] = a2.x; At[kb + 5][r] = a2.y;
    At[kb + 6][r] = a2.z; At[kb + 7][r] = a2.w;
    Bt[kb + 0][r] = b1.x; Bt[kb + 1][r] = b1.y;
    Bt[kb + 2][r] = b1.z; Bt[kb + 3][r] = b1.w;
    Bt[kb + 4][r] = b2.x; Bt[kb + 5][r] = b2.y;
    Bt[kb + 6][r] = b2.z; Bt[kb + 7][r] = b2.w;
    __syncthreads();

    // ---- compute: 8x8 microtile, 16x16 thread grid ----
    const int tx = tid & 15, ty = tid >> 4;
    const int ty8 = ty * 8, tx8 = tx * 8;

    float acc[8][8];
    #pragma unroll
    for (int x = 0; x < 8; x++)
        #pragma unroll
        for (int y = 0; y < 8; y++) acc[x][y] = 0.0f;

    #pragma unroll
    for (int kk = 0; kk < KS; kk++) {
        float4 av0 = *reinterpret_cast<const float4*>(&At[kk][ty8]);
        float4 av1 = *reinterpret_cast<const float4*>(&At[kk][ty8 + 4]);
        float4 bv0 = *reinterpret_cast<const float4*>(&Bt[kk][tx8]);
        float4 bv1 = *reinterpret_cast<const float4*>(&Bt[kk][tx8 + 4]);
        float ax[8] = {av0.x, av0.y, av0.z, av0.w, av1.x, av1.y, av1.z, av1.w};
        float bx[8] = {bv0.x, bv0.y, bv0.z, bv0.w, bv1.x, bv1.y, bv1.z, bv1.w};
        #pragma unroll
        for (int x = 0; x < 8; x++)
            #pragma unroll
            for (int y = 0; y < 8; y++)
                acc[x][y] = fmaf(ax[x], bx[y], acc[x][y]);
    }

    // ---- write partial tile + transpose (both float4-vectorized) ----
    float* G = g_gram[split];
    const int gi = a * TILE + ty8, gj = b * TILE + tx8;
    #pragma unroll
    for (int x = 0; x < 8; x++) {
        float4 o0, o1;
        o0.x = acc[x][0]; o0.y = acc[x][1]; o0.z = acc[x][2]; o0.w = acc[x][3];
        o1.x = acc[x][4]; o1.y = acc[x][5]; o1.z = acc[x][6]; o1.w = acc[x][7];
        *reinterpret_cast<float4*>(&G[(gi + x) * N2 + gj])     = o0;
        *reinterpret_cast<float4*>(&G[(gi + x) * N2 + gj + 4]) = o1;
    }
    if (a != b) {
        #pragma unroll
        for (int y = 0; y < 8; y++) {
            float4 t0, t1;
            t0.x = acc[0][y]; t0.y = acc[1][y]; t0.z = acc[2][y]; t0.w = acc[3][y];
            t1.x = acc[4][y]; t1.y = acc[5][y]; t1.z = acc[6][y]; t1.w = acc[7][y];
            *reinterpret_cast<float4*>(&G[(gj + y) * N2 + gi])     = t0;
            *reinterpret_cast<float4*>(&G[(gj + y) * N2 + gi + 4]) = t1;
        }
    }
}

// ---------------------------------------------------------------------------
// K2: per-row loss. Assembles dist from split Gram partials + norms, then
// cancellation-free dual scan + rank-narrowed binary searches over sorted k.
// ---------------------------------------------------------------------------
__global__ void __launch_bounds__(256) loss_kernel(const float* __restrict__ T)
{
    __shared__ float drow[N2], ts[N2], sv[N2], ps[N2], ss[N2];
    __shared__ float wtot[8];
    __shared__ float red[8];
    __shared__ int   ri_sh;

    const int i = blockIdx.x, t = threadIdx.x, lane = t & 31, w = t >> 5;
    const float ni = __ldg(&g_norm[i]);

    // dist row by ORIGINAL index (coalesced float2 over splits)
    {
        float2 gsum = make_float2(0.0f, 0.0f);
        #pragma unroll
        for (int s = 0; s < NSPLIT; s++) {
            float2 gv = *reinterpret_cast<const float2*>(&g_gram[s][i * N2 + 2 * t]);
            gsum.x += gv.x; gsum.y += gv.y;
        }
        float2 nv = *reinterpret_cast<const float2*>(&g_norm[2 * t]);
        drow[2 * t]     = sqrtf(fmaxf(ni + nv.x - 2.0f * gsum.x, 0.0f));
        drow[2 * t + 1] = sqrtf(fmaxf(ni + nv.y - 2.0f * gsum.y, 0.0f));
        ts[2 * t]     = g_ts[2 * t];
        ts[2 * t + 1] = g_ts[2 * t + 1];
    }
    __syncthreads();

    const float ti = __ldg(&T[i]);

    #pragma unroll
    for (int c = 0; c < 2; c++) {
        int e = t + c * 256;
        int p = g_perm[e];
        if (p == i) { sv[e] = 1.0f; ri_sh = e; }
        else        { sv[e] = __expf(-drow[p]); }
    }
    __syncthreads();

    // ---- dual scan, additions only (thread owns sorted elements 2t, 2t+1) ----
    const float v0 = sv[2 * t], v1 = sv[2 * t + 1];
    const float pair = v0 + v1;

    float p = pair;
    #pragma unroll
    for (int off = 1; off < 32; off <<= 1) {
        float tmp = __shfl_up_sync(0xffffffffu, p, off);
        if (lane >= off) p += tmp;
    }
    float q = pair;
    #pragma unroll
    for (int off = 1; off < 32; off <<= 1) {
        float tmp = __shfl_down_sync(0xffffffffu, q, off);
        if (lane + off < 32) q += tmp;
    }
    float pex = __shfl_up_sync(0xffffffffu, p, 1);
    if (lane == 0) pex = 0.0f;
    float sex = __shfl_down_sync(0xffffffffu, q, 1);
    if (lane == 31) sex = 0.0f;
    if (lane == 31) wtot[w] = p;
    __syncthreads();

    float offp = 0.0f, offs = 0.0f, total = 0.0f;
    #pragma unroll
    for (int ww = 0; ww < 8; ww++) {
        float tw = wtot[ww];
        total += tw;
        if (ww < w) offp += tw;
        if (ww > w) offs += tw;
    }
    const float bp = offp + pex;
    const float bs = offs + sex;
    ps[2 * t]     = bp + v0;
    ps[2 * t + 1] = bp + v0 + v1;
    ss[2 * t + 1] = bs + v1;
    ss[2 * t]     = bs + v1 + v0;
    __syncthreads();

    const int ri = ri_sh;   // sorted rank of i

    // ---- per-sorted-position denom via rank-narrowed binary searches ----
    float local = 0.0f;
    #pragma unroll
    for (int c = 0; c < 2; c++) {
        int r = t + c * 256;
        if (r == ri) continue;
        float ak = fabsf(ti - ts[r]);
        float denom;
        if (ak == 0.0f) {
            denom = total - 1.0f;
        } else if (r > ri) {
            int lo = ri + 1, hi = r;
            while (lo < hi) {
                int m = (lo + hi) >> 1;
                if (ts[m] - ti >= ak) hi = m; else lo = m + 1;
            }
            const int R = lo;
            int lo2 = 0, hi2 = ri;
            while (lo2 < hi2) {
                int m = (lo2 + hi2) >> 1;
                if (ti - ts[m] >= ak) lo2 = m + 1; else hi2 = m;
            }
            const float dl = (lo2 > 0) ? ps[lo2 - 1] : 0.0f;
            denom = dl + ss[R];
        } else {
            int lo = r + 1, hi = ri;
            while (lo < hi) {
                int m = (lo + hi) >> 1;
                if (ti - ts[m] >= ak) lo = m + 1; else hi = m;
            }
            const float dl = (lo > 0) ? ps[lo - 1] : 0.0f;
            int lo2 = ri + 1, hi2 = N2;
            while (lo2 < hi2) {
                int m = (lo2 + hi2) >> 1;
                if (ts[m] - ti >= ak) hi2 = m; else lo2 = m + 1;
            }
            const float dr = (lo2 < N2) ? ss[lo2] : 0.0f;
            denom = dl + dr;
        }
        local += drow[g_perm[r]] + __logf(denom);
    }

    #pragma unroll
    for (int o = 16; o > 0; o >>= 1)
        local += __shfl_xor_sync(0xffffffffu, local, o);
    if (lane == 0) red[w] = local;
    __syncthreads();
    if (t == 0) {
        float sum = 0.0f;
        #pragma unroll
        for (int k = 0; k < 8; k++) sum += red[k];
        g_part[i] = sum;
    }
}

// ---------------------------------------------------------------------------
// K3: final reduce of 512 partials -> scalar
// ---------------------------------------------------------------------------
__global__ void __launch_bounds__(256) reduce_kernel(float* __restrict__ out)
{
    __shared__ float red[8];
    const int t = threadIdx.x, lane = t & 31, w = t >> 5;
    float v = g_part[t] + g_part[t + 256];
    #pragma unroll
    for (int o = 16; o > 0; o >>= 1)
        v += __shfl_xor_sync(0xffffffffu, v, o);
    if (lane == 0) red[w] = v;
    __syncthreads();
    if (t == 0) {
        float sum = 0.0f;
        #pragma unroll
        for (int k = 0; k < 8; k++) sum += red[k];
        const float scale = 1.0f / (float(N2) * float(N2 - 1));
        *out = sum * scale;
    }
}

extern "C" void kernel_launch(void* const* d_in, const int* in_sizes, int n_in,
                              void* d_out, int out_size) {
    const float* E = (const float*)d_in[0];   // embeddings [512,256]
    const float* T = (const float*)d_in[1];   // targets    [512]
    float* out = (float*)d_out;

    dist_kernel<<<10 * NSPLIT, 256>>>(E, T);
    loss_kernel<<<N2, 256>>>(T);
    reduce_kernel<<<1, 256>>>(out);
}

// round 8
// speedup vs baseline: 1.2754x; 1.2754x over previous
#include <cuda_runtime.h>
#include <math.h>

#define N2 512
#define DM 256
#define NSPLIT 16
#define KS 16        // k-width per split block
#define NT8 8        // 8 tiles of 64 per dim; symmetric pairs = 36

__device__ float g_gram[NSPLIT][N2 * N2];   // partial Gram sums
__device__ float g_norm[N2];
__device__ float g_ts[N2];
__device__ int   g_perm[N2];
__device__ float g_part[N2];

// ---------------------------------------------------------------------------
// K1: symmetric split-k Gram GEMM. 36 tile-pairs (64x64) x 16 k-splits = 576
// blocks x 256 threads, 4x4 microtile, rotated-transpose SMEM, single chunk.
// Blocks 0..63 additionally compute target ranks + row norms.
// ---------------------------------------------------------------------------
__global__ void __launch_bounds__(256) dist_kernel(
    const float* __restrict__ E, const float* __restrict__ T)
{
    __shared__ float At[KS][68];
    __shared__ float Bt[KS][68];

    const int tid  = threadIdx.x;
    const int lane = tid & 31;
    const int w    = tid >> 5;

    // ---- fused rank-by-count + row norm on blocks 0..63 ----
    if (blockIdx.x < 64) {
        const int e = blockIdx.x * 8 + w;
        const float tv = __ldg(&T[e]);
        int cnt = 0;
        #pragma unroll
        for (int c = 0; c < 16; c++) {
            int jj = lane + c * 32;
            float o = __ldg(&T[jj]);
            cnt += (o < tv || (o == tv && jj < e)) ? 1 : 0;
        }
        float nrm = 0.0f;
        #pragma unroll
        for (int c = 0; c < 8; c++) {
            float v = __ldg(&E[e * DM + lane + c * 32]);
            nrm = fmaf(v, v, nrm);
        }
        #pragma unroll
        for (int o = 16; o > 0; o >>= 1) {
            cnt += __shfl_xor_sync(0xffffffffu, cnt, o);
            nrm += __shfl_xor_sync(0xffffffffu, nrm, o);
        }
        if (lane == 0) { g_ts[cnt] = tv; g_perm[cnt] = e; g_norm[e] = nrm; }
    }

    // ---- decode block -> (tile pair a<=b over 8 tiles; k split) ----
    const int pr    = blockIdx.x >> 4;
    const int split = blockIdx.x & 15;
    int a = 0, rem = pr, len = NT8;
    while (rem >= len) { rem -= len; a++; len--; }
    const int b = a + rem;
    const int kbase = split * KS;

    // ---- loaders: r = row in 64-tile, cq = k quarter (1 float4 each) ----
    const int r  = tid >> 2;     // 0..63
    const int cq = tid & 3;      // 0..3
    float4 av4 = *reinterpret_cast<const float4*>(E + (a * 64 + r) * DM + kbase + cq * 4);
    float4 bv4 = *reinterpret_cast<const float4*>(E + (b * 64 + r) * DM + kbase + cq * 4);

#define STORE_A(k, val) At[(k)][(r + 8 * ((k) >> 3)) & 63] = (val)
#define STORE_B(k, val) Bt[(k)][(r + 8 * ((k) >> 3)) & 63] = (val)
    {
        const int k1 = cq * 4;
        STORE_A(k1 + 0, av4.x); STORE_A(k1 + 1, av4.y);
        STORE_A(k1 + 2, av4.z); STORE_A(k1 + 3, av4.w);
        STORE_B(k1 + 0, bv4.x); STORE_B(k1 + 1, bv4.y);
        STORE_B(k1 + 2, bv4.z); STORE_B(k1 + 3, bv4.w);
    }
    __syncthreads();

    const int tx = tid & 15, ty = tid >> 4;
    const int ty4 = ty * 4, tx4 = tx * 4;

    float acc[4][4];
    #pragma unroll
    for (int x = 0; x < 4; x++)
        #pragma unroll
        for (int y = 0; y < 4; y++) acc[x][y] = 0.0f;

    #pragma unroll
    for (int kk = 0; kk < KS; kk++) {
        const int rot = 8 * (kk >> 3);
        float4 av = *reinterpret_cast<const float4*>(&At[kk][(ty4 + rot) & 63]);
        float4 bv = *reinterpret_cast<const float4*>(&Bt[kk][(tx4 + rot) & 63]);
        acc[0][0] = fmaf(av.x, bv.x, acc[0][0]);
        acc[0][1] = fmaf(av.x, bv.y, acc[0][1]);
        acc[0][2] = fmaf(av.x, bv.z, acc[0][2]);
        acc[0][3] = fmaf(av.x, bv.w, acc[0][3]);
        acc[1][0] = fmaf(av.y, bv.x, acc[1][0]);
        acc[1][1] = fmaf(av.y, bv.y, acc[1][1]);
        acc[1][2] = fmaf(av.y, bv.z, acc[1][2]);
        acc[1][3] = fmaf(av.y, bv.w, acc[1][3]);
        acc[2][0] = fmaf(av.z, bv.x, acc[2][0]);
        acc[2][1] = fmaf(av.z, bv.y, acc[2][1]);
        acc[2][2] = fmaf(av.z, bv.z, acc[2][2]);
        acc[2][3] = fmaf(av.z, bv.w, acc[2][3]);
        acc[3][0] = fmaf(av.w, bv.x, acc[3][0]);
        acc[3][1] = fmaf(av.w, bv.y, acc[3][1]);
        acc[3][2] = fmaf(av.w, bv.z, acc[3][2]);
        acc[3][3] = fmaf(av.w, bv.w, acc[3][3]);
    }

    // ---- write partial tile (+ transpose for off-diagonal pairs) ----
    float* G = g_gram[split];
    const int gi = a * 64 + ty4, gj = b * 64 + tx4;
    #pragma unroll
    for (int x = 0; x < 4; x++) {
        float4 o;
        o.x = acc[x][0]; o.y = acc[x][1]; o.z = acc[x][2]; o.w = acc[x][3];
        *reinterpret_cast<float4*>(&G[(gi + x) * N2 + gj]) = o;
    }
    if (a != b) {
        #pragma unroll
        for (int y = 0; y < 4; y++) {
            float4 tr;
            tr.x = acc[0][y]; tr.y = acc[1][y]; tr.z = acc[2][y]; tr.w = acc[3][y];
            *reinterpret_cast<float4*>(&G[(gj + y) * N2 + gi]) = tr;
        }
    }
}

// ---------------------------------------------------------------------------
// K2: per-row loss. Assembles dist from split Gram partials + norms;
// cancellation-free dual scan; ONE binary search per element (opposite side)
// + equality-run walk for the same-side boundary.
// ---------------------------------------------------------------------------
__global__ void __launch_bounds__(256) loss_kernel(const float* __restrict__ T)
{
    __shared__ float drow[N2], ts[N2], sv[N2], ds[N2], ps[N2], ss[N2];
    __shared__ float wtot[8];
    __shared__ float red[8];
    __shared__ int   ri_sh;

    const int i = blockIdx.x, t = threadIdx.x, lane = t & 31, w = t >> 5;
    const float ni = __ldg(&g_norm[i]);

    // dist row by ORIGINAL index (coalesced float2 over splits)
    {
        float2 gsum = make_float2(0.0f, 0.0f);
        #pragma unroll
        for (int s = 0; s < NSPLIT; s++) {
            float2 gv = *reinterpret_cast<const float2*>(&g_gram[s][i * N2 + 2 * t]);
            gsum.x += gv.x; gsum.y += gv.y;
        }
        float2 nv = *reinterpret_cast<const float2*>(&g_norm[2 * t]);
        drow[2 * t]     = sqrtf(fmaxf(ni + nv.x - 2.0f * gsum.x, 0.0f));
        drow[2 * t + 1] = sqrtf(fmaxf(ni + nv.y - 2.0f * gsum.y, 0.0f));
        ts[2 * t]     = g_ts[2 * t];
        ts[2 * t + 1] = g_ts[2 * t + 1];
    }
    __syncthreads();

    const float ti = __ldg(&T[i]);

    #pragma unroll
    for (int c = 0; c < 2; c++) {
        int e = t + c * 256;
        int p = g_perm[e];
        float d = drow[p];
        ds[e] = d;
        if (p == i) { sv[e] = 1.0f; ri_sh = e; }
        else        { sv[e] = __expf(-d); }
    }
    __syncthreads();

    // ---- dual scan, additions only (thread owns sorted elements 2t, 2t+1) ----
    const float v0 = sv[2 * t], v1 = sv[2 * t + 1];
    const float pair = v0 + v1;

    float p = pair;
    #pragma unroll
    for (int off = 1; off < 32; off <<= 1) {
        float tmp = __shfl_up_sync(0xffffffffu, p, off);
        if (lane >= off) p += tmp;
    }
    float q = pair;
    #pragma unroll
    for (int off = 1; off < 32; off <<= 1) {
        float tmp = __shfl_down_sync(0xffffffffu, q, off);
        if (lane + off < 32) q += tmp;
    }
    float pex = __shfl_up_sync(0xffffffffu, p, 1);
    if (lane == 0) pex = 0.0f;
    float sex = __shfl_down_sync(0xffffffffu, q, 1);
    if (lane == 31) sex = 0.0f;
    if (lane == 31) wtot[w] = p;
    __syncthreads();

    float offp = 0.0f, offs = 0.0f, total = 0.0f;
    #pragma unroll
    for (int ww = 0; ww < 8; ww++) {
        float tw = wtot[ww];
        total += tw;
        if (ww < w) offp += tw;
        if (ww > w) offs += tw;
    }
    const float bp = offp + pex;
    const float bs = offs + sex;
    ps[2 * t]     = bp + v0;
    ps[2 * t + 1] = bp + v0 + v1;
    ss[2 * t + 1] = bs + v1;
    ss[2 * t]     = bs + v1 + v0;
    __syncthreads();

    const int ri = ri_sh;   // sorted rank of i

    // ---- per-sorted-position denom: 1 binary search + equality-run walk ----
    float local = 0.0f;
    #pragma unroll
    for (int c = 0; c < 2; c++) {
        int r = t + c * 256;
        if (r == ri) continue;
        float denom;
        if (r > ri) {
            const float ak = ts[r] - ti;        // == fabsf, sign-exact
            if (ak == 0.0f) {
                denom = total - 1.0f;
            } else {
                // same-side boundary: walk back equality run (usually 0 steps)
                int R = r;
                while (R > ri + 1 && (ts[R - 1] - ti >= ak)) R--;
                // opposite side: first m in [0, ri] with fl(ti-ts[m]) < ak
                int lo2 = 0, hi2 = ri;
                while (lo2 < hi2) {
                    int m = (lo2 + hi2) >> 1;
                    if (ti - ts[m] >= ak) lo2 = m + 1; else hi2 = m;
                }
                const float dl = (lo2 > 0) ? ps[lo2 - 1] : 0.0f;
                denom = dl + ss[R];
            }
        } else {
            const float ak = ti - ts[r];
            if (ak == 0.0f) {
                denom = total - 1.0f;
            } else {
                // same-side boundary: walk forward equality run
                int lo = r + 1;
                while (lo <= ri && (ti - ts[lo] >= ak)) lo++;
                const float dl = ps[lo - 1];    // lo-1 >= r >= 0
                // opposite side: first m in (ri, N2) with fl(ts[m]-ti) >= ak
                int lo2 = ri + 1, hi2 = N2;
                while (lo2 < hi2) {
                    int m = (lo2 + hi2) >> 1;
                    if (ts[m] - ti >= ak) hi2 = m; else lo2 = m + 1;
                }
                const float dr = (lo2 < N2) ? ss[lo2] : 0.0f;
                denom = dl + dr;
            }
        }
        local += ds[r] + __logf(denom);
    }

    #pragma unroll
    for (int o = 16; o > 0; o >>= 1)
        local += __shfl_xor_sync(0xffffffffu, local, o);
    if (lane == 0) red[w] = local;
    __syncthreads();
    if (t == 0) {
        float sum = 0.0f;
        #pragma unroll
        for (int k = 0; k < 8; k++) sum += red[k];
        g_part[i] = sum;
    }
}

// ---------------------------------------------------------------------------
// K3: final reduce of 512 partials -> scalar
// ---------------------------------------------------------------------------
__global__ void __launch_bounds__(256) reduce_kernel(float* __restrict__ out)
{
    __shared__ float red[8];
    const int t = threadIdx.x, lane = t & 31, w = t >> 5;
    float v = g_part[t] + g_part[t + 256];
    #pragma unroll
    for (int o = 16; o > 0; o >>= 1)
        v += __shfl_xor_sync(0xffffffffu, v, o);
    if (lane == 0) red[w] = v;
    __syncthreads();
    if (t == 0) {
        float sum = 0.0f;
        #pragma unroll
        for (int k = 0; k < 8; k++) sum += red[k];
        const float scale = 1.0f / (float(N2) * float(N2 - 1));
        *out = sum * scale;
    }
}

extern "C" void kernel_launch(void* const* d_in, const int* in_sizes, int n_in,
                              void* d_out, int out_size) {
    const float* E = (const float*)d_in[0];   // embeddings [512,256]
    const float* T = (const float*)d_in[1];   // targets    [512]
    float* out = (float*)d_out;

    dist_kernel<<<36 * NSPLIT, 256>>>(E, T);
    loss_kernel<<<N2, 256>>>(T);
    reduce_kernel<<<1, 256>>>(out);
}